// round 17
// baseline (speedup 1.0000x reference)
#include <cuda_runtime.h>
#include <cuda_fp16.h>
#include <cstdint>

// B=1024, T=200, IN=H=128. rows = 204800.
__device__ __half g_xall16[(size_t)204800 * 384];   // [flat row][xu|xr|xg] fp16, biases folded
__device__ float g_logits[204800];

__device__ __forceinline__ uint32_t smem_u32(const void* p) {
    return (uint32_t)__cvta_generic_to_shared(p);
}
__device__ __forceinline__ void ldmatrix_x4(uint32_t a[4], uint32_t addr) {
    asm volatile("ldmatrix.sync.aligned.m8n8.x4.shared.b16 {%0,%1,%2,%3}, [%4];"
                 : "=r"(a[0]), "=r"(a[1]), "=r"(a[2]), "=r"(a[3]) : "r"(addr));
}
__device__ __forceinline__ void ldmatrix_x4_trans(uint32_t a[4], uint32_t addr) {
    asm volatile("ldmatrix.sync.aligned.m8n8.x4.trans.shared.b16 {%0,%1,%2,%3}, [%4];"
                 : "=r"(a[0]), "=r"(a[1]), "=r"(a[2]), "=r"(a[3]) : "r"(addr));
}
__device__ __forceinline__ void mma16816(float c[4], const uint32_t a[4], uint32_t b0, uint32_t b1) {
    asm volatile("mma.sync.aligned.m16n8k16.row.col.f32.f16.f16.f32 "
                 "{%0,%1,%2,%3},{%4,%5,%6,%7},{%8,%9},{%0,%1,%2,%3};"
                 : "+f"(c[0]), "+f"(c[1]), "+f"(c[2]), "+f"(c[3])
                 : "r"(a[0]), "r"(a[1]), "r"(a[2]), "r"(a[3]), "r"(b0), "r"(b1));
}
__device__ __forceinline__ uint32_t f2h2(float x, float y) {
    __half2 h = __floats2half2_rn(x, y);
    return *reinterpret_cast<uint32_t*>(&h);
}
__device__ __forceinline__ float tanhapx(float x) {
    float y; asm("tanh.approx.f32 %0, %1;" : "=f"(y) : "f"(x)); return y;
}
__device__ __forceinline__ void cp_async16(uint32_t dst, const void* src) {
    asm volatile("cp.async.cg.shared.global [%0], [%1], 16;" :: "r"(dst), "l"(src));
}
__device__ __forceinline__ void cp_commit() { asm volatile("cp.async.commit_group;"); }
__device__ __forceinline__ void cp_wait0()  { asm volatile("cp.async.wait_group 0;" ::: "memory"); }
__device__ __forceinline__ void cp_wait1()  { asm volatile("cp.async.wait_group 1;" ::: "memory"); }

// ================= K0: dummies (keep ncu capture on k3_scan = 4th launch) =================
__global__ void k0_dummy() {}

// ================= K1: logits + x projections, cp.async input pipeline (frozen) =================
#define K1_RAWH_OFF 32768
#define K1_TG_OFF   65536
#define K1_HS_OFF   82944
#define K1_SWB_OFF  100352
#define K1_LGP_OFF  115712
#define K1_SMEM     116736
#define K1_TILES    3200

__global__ __launch_bounds__(512) void k1_ff(
    const float* __restrict__ targets, const float* __restrict__ hist,
    const float* __restrict__ Ww,  const float* __restrict__ Wb,
    const float* __restrict__ xuw, const float* __restrict__ xub,
    const float* __restrict__ xrw, const float* __restrict__ xrb,
    const float* __restrict__ xgw, const float* __restrict__ xgb)
{
    extern __shared__ char sm[];
    float4* rawT = (float4*)sm;
    float4* rawH = (float4*)(sm + K1_RAWH_OFF);
    __half* tg16 = (__half*)(sm + K1_TG_OFF);
    __half* hs16 = (__half*)(sm + K1_HS_OFF);
    uint32_t* swb = (uint32_t*)(sm + K1_SWB_OFF);
    float* lgp = (float*)(sm + K1_LGP_OFF);

    const int t = threadIdx.x, w = t >> 5, lane = t & 31;
    const int q = lane & 3, l4 = lane >> 2;
    const int g = w >> 2;
    const int cb = 32 * (w & 3);
    const bool is_logit = (g == 0);

    const float* W  = (g == 0) ? Ww  : (g == 1) ? xuw : (g == 2) ? xrw : xgw;
    const float* Bv = (g == 0) ? Wb  : (g == 1) ? xub : (g == 2) ? xrb : xgb;

    uint32_t bfr[4][8][2];
    float2 bs[4];
    #pragma unroll
    for (int ct = 0; ct < 4; ct++) {
        const int n = cb + 8 * ct + l4;
        bs[ct] = *(const float2*)&Bv[cb + 8 * ct + 2 * q];
        #pragma unroll
        for (int kt = 0; kt < 8; kt++) {
            float2 wa = *(const float2*)&W[n * 128 + kt * 16 + 2 * q];
            float2 wb = *(const float2*)&W[n * 128 + kt * 16 + 2 * q + 8];
            bfr[ct][kt][0] = f2h2(wa.x, wa.y);
            bfr[ct][kt][1] = f2h2(wb.x, wb.y);
        }
    }

    const uint32_t rawTu = smem_u32(rawT), rawHu = smem_u32(rawH);
    const uint32_t abase = smem_u32(is_logit ? tg16 : hs16)
                         + (lane & 15) * 272 + (lane >> 4) * 16;
    uint32_t* swbw = swb + (w - 4) * 320;
    const int gc0 = (g - 1) * 128 + cb;

    {
        const size_t base = (size_t)blockIdx.x * 64 * 128;
        #pragma unroll
        for (int j = 0; j < 4; j++) {
            int i = t + 512 * j;
            cp_async16(rawTu + 16 * i, &targets[base + 4 * i]);
            cp_async16(rawHu + 16 * i, &hist[base + 4 * i]);
        }
        cp_commit();
    }

    for (int tile = blockIdx.x; tile < K1_TILES; tile += 148) {
        const size_t row0 = (size_t)tile * 64;
        cp_wait0();
        __syncthreads();

        #pragma unroll
        for (int j = 0; j < 4; j++) {
            int i = t + 512 * j;
            int r = i >> 5, c = (i & 31) * 4;
            float4 v = rawT[i];
            uint2 p; p.x = f2h2(v.x, v.y); p.y = f2h2(v.z, v.w);
            *(uint2*)&tg16[r * 136 + c] = p;
            v = rawH[i];
            p.x = f2h2(v.x, v.y); p.y = f2h2(v.z, v.w);
            *(uint2*)&hs16[r * 136 + c] = p;
        }
        __syncthreads();

        if (tile + 148 < K1_TILES) {
            const size_t nbase = (size_t)(tile + 148) * 64 * 128;
            #pragma unroll
            for (int j = 0; j < 4; j++) {
                int i = t + 512 * j;
                cp_async16(rawTu + 16 * i, &targets[nbase + 4 * i]);
                cp_async16(rawHu + 16 * i, &hist[nbase + 4 * i]);
            }
        }
        cp_commit();

        #pragma unroll
        for (int mt = 0; mt < 4; mt++) {
            float acc[4][4];
            #pragma unroll
            for (int ct = 0; ct < 4; ct++) {
                if (is_logit) {
                    acc[ct][0] = acc[ct][1] = acc[ct][2] = acc[ct][3] = 0.f;
                } else {
                    acc[ct][0] = bs[ct].x; acc[ct][1] = bs[ct].y;
                    acc[ct][2] = bs[ct].x; acc[ct][3] = bs[ct].y;
                }
            }
            const uint32_t ab = abase + mt * 4352;
            #pragma unroll
            for (int kc = 0; kc < 2; kc++) {
                uint32_t af[4][4];
                #pragma unroll
                for (int k4 = 0; k4 < 4; k4++)
                    ldmatrix_x4(af[k4], ab + (4 * kc + k4) * 32);
                #pragma unroll
                for (int ct = 0; ct < 4; ct++)
                    #pragma unroll
                    for (int k4 = 0; k4 < 4; k4++)
                        mma16816(acc[ct], af[k4], bfr[ct][4 * kc + k4][0], bfr[ct][4 * kc + k4][1]);
            }
            const int r0 = mt * 16 + l4, r1 = r0 + 8;
            if (is_logit) {
                float p0 = 0.f, p1 = 0.f;
                #pragma unroll
                for (int ct = 0; ct < 4; ct++) {
                    const int col = cb + 8 * ct + 2 * q;
                    float2 h0 = __half22float2(*(const __half2*)&hs16[r0 * 136 + col]);
                    float2 h1 = __half22float2(*(const __half2*)&hs16[r1 * 136 + col]);
                    p0 += (acc[ct][0] + bs[ct].x) * h0.x + (acc[ct][1] + bs[ct].y) * h0.y;
                    p1 += (acc[ct][2] + bs[ct].x) * h1.x + (acc[ct][3] + bs[ct].y) * h1.y;
                }
                p0 += __shfl_xor_sync(~0u, p0, 1); p0 += __shfl_xor_sync(~0u, p0, 2);
                p1 += __shfl_xor_sync(~0u, p1, 1); p1 += __shfl_xor_sync(~0u, p1, 2);
                if (q == 0) {
                    lgp[w * 64 + r0] = p0;
                    lgp[w * 64 + r1] = p1;
                }
            } else {
                #pragma unroll
                for (int ct = 0; ct < 4; ct++) {
                    swbw[l4 * 20 + ct * 4 + q]       = f2h2(acc[ct][0], acc[ct][1]);
                    swbw[(l4 + 8) * 20 + ct * 4 + q] = f2h2(acc[ct][2], acc[ct][3]);
                }
                __syncwarp();
                #pragma unroll
                for (int i = lane; i < 256; i += 32) {
                    int row = i >> 4, c = i & 15;
                    uint32_t v = swbw[row * 20 + c];
                    *(uint32_t*)&g_xall16[(row0 + mt * 16 + row) * 384 + gc0 + 2 * c] = v;
                }
                __syncwarp();
            }
        }
        __syncthreads();
        if (t < 64)
            g_logits[row0 + t] = lgp[t] + lgp[64 + t] + lgp[128 + t] + lgp[192 + t];
    }
}

// ================= K3: GRU scan — cp.async x-feed, depth-2 mma chains, fused softmax + linear =================
#define XPAD 196                    // uint32 row stride (784 B)
#define XBUFB (8 * 784)             // bytes per x buffer = 6272

__global__ __launch_bounds__(256) void k3_scan(
    const float* __restrict__ targets,
    const float* __restrict__ huw, const float* __restrict__ hub,
    const float* __restrict__ hrw, const float* __restrict__ hrb,
    const float* __restrict__ hgw, const float* __restrict__ hgb,
    const float* __restrict__ lnw, const float* __restrict__ lnb,
    float* __restrict__ out)
{
    __shared__ __align__(16) __half hT[2][128 * 8];
    __shared__ __align__(16) uint32_t xbuf[3][8 * XPAD];
    __shared__ __align__(16) float attall[8][200];
    __shared__ __align__(16) float xs[8][260];
    const int t = threadIdx.x, w = t >> 5, lane = t & 31;
    const int q = lane & 3, l4 = lane >> 2;
    const size_t rowb = (size_t)blockIdx.x * 8;

    // ---- weight A-fragments (registers, once) ----
    uint32_t afr[3][8][4];
    float bias_[3][2];
    #pragma unroll
    for (int g = 0; g < 3; g++) {
        const float* W  = (g == 0) ? huw : (g == 1) ? hrw : hgw;
        const float* Bv = (g == 0) ? hub : (g == 1) ? hrb : hgb;
        bias_[g][0] = Bv[16 * w + l4];
        bias_[g][1] = Bv[16 * w + l4 + 8];
        #pragma unroll
        for (int kt = 0; kt < 8; kt++) {
            const float* bp = W + (16 * w + l4) * 128 + kt * 16 + 2 * q;
            float2 v0 = *(const float2*)(bp);
            float2 v2 = *(const float2*)(bp + 8);
            float2 v1 = *(const float2*)(bp + 8 * 128);
            float2 v3 = *(const float2*)(bp + 8 * 128 + 8);
            afr[g][kt][0] = f2h2(v0.x, v0.y);
            afr[g][kt][1] = f2h2(v1.x, v1.y);
            afr[g][kt][2] = f2h2(v2.x, v2.y);
            afr[g][kt][3] = f2h2(v3.x, v3.y);
        }
    }
    for (int i = t; i < 2048; i += 256) ((__half*)hT)[i] = __float2half(0.f);

    // ---- fused softmax: warp w handles batch row rowb+w ----
    {
        const float* lg = &g_logits[(rowb + w) * 200];
        float mx = -1e30f;
        for (int i = lane; i < 200; i += 32) mx = fmaxf(mx, lg[i]);
        #pragma unroll
        for (int o = 16; o; o >>= 1) mx = fmaxf(mx, __shfl_xor_sync(~0u, mx, o));
        float s = 0.f;
        for (int i = lane; i < 200; i += 32) {
            float e = __expf(lg[i] - mx);
            attall[w][i] = e;
            s += e;
        }
        #pragma unroll
        for (int o = 16; o; o >>= 1) s += __shfl_xor_sync(~0u, s, o);
        float inv = __fdividef(1.f, s);
        for (int i = lane; i < 200; i += 32) attall[w][i] *= inv;
    }

    // ---- cp.async x-feed mapping (384 x 16B chunks/step) ----
    const int c0 = t, c1 = t + 256;
    const bool has1 = (c1 < 384);
    const int r0c = c0 / 48, o0 = c0 % 48;
    const int r1c = c1 / 48, o1 = c1 % 48;
    const char* src0 = (const char*)g_xall16 + ((rowb + r0c) * 200) * 768 + o0 * 16;
    const char* src1 = (const char*)g_xall16 + ((rowb + r1c) * 200) * 768 + o1 * 16;
    const uint32_t xbu = smem_u32(xbuf);
    const uint32_t dst0 = xbu + r0c * 784 + o0 * 16;
    const uint32_t dst1 = xbu + r1c * 784 + o1 * 16;

    cp_async16(dst0, src0);
    if (has1) cp_async16(dst1, src1);
    cp_commit();
    cp_async16(dst0 + XBUFB, src0 + 768);
    if (has1) cp_async16(dst1 + XBUFB, src1 + 768);
    cp_commit();
    src0 += 2 * 768; src1 += 2 * 768;
    cp_wait1();
    __syncthreads();

    float hm[4] = {0.f, 0.f, 0.f, 0.f};
    const uint32_t hTb = smem_u32(hT) + lane * 16;
    const int colA = 16 * w + l4, colB = colA + 8;
    int buf = 0, buf2 = 2;

    // att for step 0 pre-loaded
    float attv0 = attall[2 * q][0], attv1 = attall[2 * q + 1][0];

    for (int step = 0; step < 200; step++) {
        const int rb = step & 1, wb = 1 - rb;

        if (step < 198) {
            cp_async16(dst0 + buf2 * XBUFB, src0);
            if (has1) cp_async16(dst1 + buf2 * XBUFB, src1);
            src0 += 768; src1 += 768;
        }
        cp_commit();

        // B-frags from hT
        uint32_t bf[8][2];
        #pragma unroll
        for (int j = 0; j < 4; j++) {
            uint32_t r4[4];
            ldmatrix_x4_trans(r4, hTb + rb * 2048 + j * 512);
            bf[2 * j][0] = r4[0]; bf[2 * j][1] = r4[1];
            bf[2 * j + 1][0] = r4[2]; bf[2 * j + 1][1] = r4[3];
        }
        // 12 interleaved chains, depth 2: chain (g,c) covers kt=c then kt=c+4
        float ac[3][4][4];
        #pragma unroll
        for (int g = 0; g < 3; g++)
            #pragma unroll
            for (int c = 0; c < 4; c++)
                ac[g][c][0] = ac[g][c][1] = ac[g][c][2] = ac[g][c][3] = 0.f;
        #pragma unroll
        for (int c = 0; c < 4; c++) {
            mma16816(ac[0][c], afr[0][c], bf[c][0], bf[c][1]);
            mma16816(ac[1][c], afr[1][c], bf[c][0], bf[c][1]);
            mma16816(ac[2][c], afr[2][c], bf[c][0], bf[c][1]);
        }
        #pragma unroll
        for (int c = 0; c < 4; c++) {
            mma16816(ac[0][c], afr[0][c + 4], bf[c + 4][0], bf[c + 4][1]);
            mma16816(ac[1][c], afr[1][c + 4], bf[c + 4][0], bf[c + 4][1]);
            mma16816(ac[2][c], afr[2][c + 4], bf[c + 4][0], bf[c + 4][1]);
        }

        // x-gather from smem ring (independent, overlaps mma)
        const char* xb = (const char*)xbuf + buf * XBUFB;
        float xu4[4], xr4[4], xg4[4];
        #pragma unroll
        for (int c = 0; c < 4; c++) {
            const int bofs = (2 * q + (c & 1)) * 784 + ((c >> 1) ? colB : colA) * 2;
            xu4[c] = __half2float(*(const __half*)(xb + bofs));
            xr4[c] = __half2float(*(const __half*)(xb + bofs + 256));
            xg4[c] = __half2float(*(const __half*)(xb + bofs + 512));
        }

        float hn[4];
        #pragma unroll
        for (int c = 0; c < 4; c++) {
            const int hi = c >> 1;
            const float ae = (c & 1) ? attv1 : attv0;
            float su = ((ac[0][0][c] + ac[0][1][c]) + (ac[0][2][c] + ac[0][3][c])) + (xu4[c] + bias_[0][hi]);
            float sr = ((ac[1][0][c] + ac[1][1][c]) + (ac[1][2][c] + ac[1][3][c])) + (xr4[c] + bias_[1][hi]);
            float sg = ((ac[2][0][c] + ac[2][1][c]) + (ac[2][2][c] + ac[2][3][c])) + bias_[2][hi];
            float u = fmaf(tanhapx(0.5f * su), 0.5f, 0.5f) * ae;
            float r = fmaf(tanhapx(0.5f * sr), 0.5f, 0.5f);
            float gg = tanhapx(fmaf(r, sg, xg4[c]));
            hn[c] = fmaf(u, gg - hm[c], hm[c]);
        }
        *(uint32_t*)((char*)hT[wb] + colA * 16 + 4 * q) = f2h2(hn[0], hn[1]);
        *(uint32_t*)((char*)hT[wb] + colB * 16 + 4 * q) = f2h2(hn[2], hn[3]);
        hm[0] = hn[0]; hm[1] = hn[1]; hm[2] = hn[2]; hm[3] = hn[3];

        // prefetch next step's att (off-chain)
        if (step < 199) {
            attv0 = attall[2 * q][step + 1];
            attv1 = attall[2 * q + 1][step + 1];
        }

        cp_wait1();
        __syncthreads();

        buf = (buf == 2) ? 0 : buf + 1;
        buf2 = (buf2 == 2) ? 0 : buf2 + 1;
    }

    // ---- fused final linear: out = [h, targets[:,0]] @ ln2_w^T + b ----
    xs[2 * q][colA]     = hm[0];
    xs[2 * q + 1][colA] = hm[1];
    xs[2 * q][colB]     = hm[2];
    xs[2 * q + 1][colB] = hm[3];
    for (int i = t; i < 1024; i += 256) {
        int bb = i >> 7, c = i & 127;
        xs[bb][128 + c] = targets[(size_t)(rowb + bb) * 200 * 128 + c];
    }
    __syncthreads();
    const int col = t & 127, grp = t >> 7;
    float acc4[4];
    const float bv = lnb[col];
    #pragma unroll
    for (int i = 0; i < 4; i++) acc4[i] = bv;
    const float4* wr = (const float4*)(lnw + (size_t)col * 256);
    #pragma unroll 4
    for (int k = 0; k < 64; k++) {
        float4 wv = wr[k];
        #pragma unroll
        for (int i = 0; i < 4; i++) {
            float4 xv = *(const float4*)&xs[grp * 4 + i][k * 4];
            acc4[i] += wv.x * xv.x + wv.y * xv.y + wv.z * xv.z + wv.w * xv.w;
        }
    }
    #pragma unroll
    for (int i = 0; i < 4; i++)
        out[(rowb + grp * 4 + i) * 128 + col] = acc4[i];
}

extern "C" void kernel_launch(void* const* d_in, const int* in_sizes, int n_in,
                              void* d_out, int out_size)
{
    const float* targets = (const float*)d_in[0];
    const float* hist    = (const float*)d_in[1];
    const float* Ww  = (const float*)d_in[2];  const float* Wb  = (const float*)d_in[3];
    const float* xuw = (const float*)d_in[4];  const float* xub = (const float*)d_in[5];
    const float* huw = (const float*)d_in[6];  const float* hub = (const float*)d_in[7];
    const float* xrw = (const float*)d_in[8];  const float* xrb = (const float*)d_in[9];
    const float* hrw = (const float*)d_in[10]; const float* hrb = (const float*)d_in[11];
    const float* xgw = (const float*)d_in[12]; const float* xgb = (const float*)d_in[13];
    const float* hgw = (const float*)d_in[14]; const float* hgb = (const float*)d_in[15];
    const float* lnw = (const float*)d_in[16]; const float* lnb = (const float*)d_in[17];
    float* out = (float*)d_out;

    cudaFuncSetAttribute(k1_ff, cudaFuncAttributeMaxDynamicSharedMemorySize, K1_SMEM);

    k0_dummy<<<1, 32>>>();
    k0_dummy<<<1, 32>>>();
    k1_ff<<<148, 512, K1_SMEM>>>(targets, hist, Ww, Wb, xuw, xub, xrw, xrb, xgw, xgb);
    k3_scan<<<128, 256>>>(targets, huw, hub, hrw, hrb, hgw, hgb, lnw, lnb, out);
}